// round 1
// baseline (speedup 1.0000x reference)
#include <cuda_runtime.h>
#include <math.h>

// Problem constants (fixed by the reference: b=4, n=4096, d=1024)
#define B_BATCH 4
#define N_SEQ   4096
#define D_DIM   1024
#define M_TOK   (B_BATCH * N_SEQ)   // 16384 token rows
#define TWO_D   (2 * D_DIM)         // 2048

// Scratch (device globals: allocation-free per harness rules)
__device__ float g_is[(size_t)M_TOK * TWO_D];  // input_state (u before gamma), 128 MB
__device__ float g_nu[(size_t)M_TOK * D_DIM];  // sigmoid(nu logits), 64 MB
__device__ float g_h [(size_t)M_TOK * TWO_D];  // [h_r | h_i] per row, 128 MB

// ---------------------------------------------------------------------------
// GEMM: C[M,N] = A[M,K] * W[N,K]^T + bias[N]   (both A and W are K-major)
// Tile 128x128x8, 256 threads, 8x8 accum per thread. ACT=1 applies sigmoid.
// M % 128 == 0, N % 128 == 0, K % 8 == 0 guaranteed by problem sizes.
// ---------------------------------------------------------------------------
template <int ACT>
__global__ __launch_bounds__(256)
void gemm_tn_kernel(const float* __restrict__ A,
                    const float* __restrict__ W,
                    const float* __restrict__ bias,
                    float* __restrict__ C,
                    int M, int N, int K) {
    __shared__ float As[8][128];
    __shared__ float Ws[8][128];

    const int tx = threadIdx.x & 15;   // 0..15 -> 8 cols each
    const int ty = threadIdx.x >> 4;   // 0..15 -> 8 rows each
    const int bm = blockIdx.y * 128;
    const int bn = blockIdx.x * 128;

    // Loader mapping: 2 threads per tile-row, float4 each (8 k-floats/row)
    const int lrow = threadIdx.x >> 1;        // 0..127
    const int lk4  = (threadIdx.x & 1) << 2;  // 0 or 4

    const float* Aptr = A + (size_t)(bm + lrow) * K + lk4;
    const float* Wptr = W + (size_t)(bn + lrow) * K + lk4;

    float acc[8][8];
#pragma unroll
    for (int i = 0; i < 8; i++)
#pragma unroll
        for (int j = 0; j < 8; j++) acc[i][j] = 0.0f;

    for (int k0 = 0; k0 < K; k0 += 8) {
        float4 av = *reinterpret_cast<const float4*>(Aptr + k0);
        float4 wv = *reinterpret_cast<const float4*>(Wptr + k0);
        __syncthreads();  // previous iteration's reads complete
        As[lk4 + 0][lrow] = av.x; As[lk4 + 1][lrow] = av.y;
        As[lk4 + 2][lrow] = av.z; As[lk4 + 3][lrow] = av.w;
        Ws[lk4 + 0][lrow] = wv.x; Ws[lk4 + 1][lrow] = wv.y;
        Ws[lk4 + 2][lrow] = wv.z; Ws[lk4 + 3][lrow] = wv.w;
        __syncthreads();
#pragma unroll
        for (int k = 0; k < 8; k++) {
            float a[8], b[8];
#pragma unroll
            for (int i = 0; i < 8; i++) a[i] = As[k][ty * 8 + i];
#pragma unroll
            for (int j = 0; j < 8; j++) b[j] = Ws[k][tx * 8 + j];
#pragma unroll
            for (int i = 0; i < 8; i++)
#pragma unroll
                for (int j = 0; j < 8; j++) acc[i][j] = fmaf(a[i], b[j], acc[i][j]);
        }
    }

#pragma unroll
    for (int i = 0; i < 8; i++) {
        const size_t row = (size_t)(bm + ty * 8 + i);
#pragma unroll
        for (int j = 0; j < 8; j++) {
            const int col = bn + tx * 8 + j;
            float v = acc[i][j] + bias[col];
            if (ACT == 1) v = 1.0f / (1.0f + expf(-v));
            C[row * N + col] = v;
        }
    }
}

// ---------------------------------------------------------------------------
// Sequential diagonal complex scan: one thread per (batch, channel).
//   lam = nu * (cos(theta) + i sin(theta)),  u = gamma * (is[2j] + i is[2j+1])
//   h_t = lam_t * h_{t-1} + u_t
// Writes g_h[row, j] = Re(h), g_h[row, 1024 + j] = Im(h).
// ---------------------------------------------------------------------------
__global__ __launch_bounds__(128)
void scan_kernel(const float* __restrict__ theta_log,
                 const float* __restrict__ gamma_log) {
    const int gid = blockIdx.x * blockDim.x + threadIdx.x;  // 0..4095
    if (gid >= B_BATCH * D_DIM) return;
    const int b = gid >> 10;        // batch
    const int j = gid & (D_DIM - 1);

    const float theta = expf(theta_log[j]);
    const float ct = cosf(theta);
    const float st = sinf(theta);
    const float gm = expf(gamma_log[j]);

    float hr = 0.0f, hi = 0.0f;

    size_t nu_ofs = (size_t)b * N_SEQ * D_DIM + j;
    size_t is_ofs = (size_t)b * N_SEQ * TWO_D + 2 * j;
    size_t h_ofs  = (size_t)b * N_SEQ * TWO_D + j;

    for (int t = 0; t < N_SEQ; t++) {
        const float nu = g_nu[nu_ofs];
        const float2 uv = *reinterpret_cast<const float2*>(&g_is[is_ofs]);
        const float lr = nu * ct;
        const float li = nu * st;
        const float ur = gm * uv.x;
        const float ui = gm * uv.y;
        const float nhr = lr * hr - li * hi + ur;
        const float nhi = lr * hi + li * hr + ui;
        hr = nhr; hi = nhi;
        g_h[h_ofs]         = hr;
        g_h[h_ofs + D_DIM] = hi;
        nu_ofs += D_DIM;
        is_ofs += TWO_D;
        h_ofs  += TWO_D;
    }
}

// ---------------------------------------------------------------------------
// Launch
// ---------------------------------------------------------------------------
extern "C" void kernel_launch(void* const* d_in, const int* in_sizes, int n_in,
                              void* d_out, int out_size) {
    const float* x         = (const float*)d_in[0];  // (4, 4096, 1024)
    const float* theta_log = (const float*)d_in[1];  // (1024,)
    const float* gamma_log = (const float*)d_in[2];  // (1024,)
    const float* nu_w      = (const float*)d_in[3];  // (1024, 1024)
    const float* nu_b      = (const float*)d_in[4];  // (1024,)
    const float* in_w      = (const float*)d_in[5];  // (2048, 1024)
    const float* in_b      = (const float*)d_in[6];  // (2048,)
    const float* out_w     = (const float*)d_in[7];  // (1024, 2048)
    const float* out_b     = (const float*)d_in[8];  // (1024,)
    float* out = (float*)d_out;                      // (4, 4096, 1024)

    float *p_is = nullptr, *p_nu = nullptr, *p_h = nullptr;
    cudaGetSymbolAddress((void**)&p_is, g_is);
    cudaGetSymbolAddress((void**)&p_nu, g_nu);
    cudaGetSymbolAddress((void**)&p_h,  g_h);

    // GEMM1: input_state = x @ in_w^T + in_b   -> g_is  (16384 x 2048)
    {
        dim3 grid(TWO_D / 128, M_TOK / 128);
        gemm_tn_kernel<0><<<grid, 256>>>(x, in_w, in_b, p_is, M_TOK, TWO_D, D_DIM);
    }
    // GEMM2: nu = sigmoid(x @ nu_w^T + nu_b)   -> g_nu  (16384 x 1024)
    {
        dim3 grid(D_DIM / 128, M_TOK / 128);
        gemm_tn_kernel<1><<<grid, 256>>>(x, nu_w, nu_b, p_nu, M_TOK, D_DIM, D_DIM);
    }
    // Scan -> g_h (16384 x 2048, [h_r | h_i])
    {
        scan_kernel<<<(B_BATCH * D_DIM) / 128, 128>>>(theta_log, gamma_log);
    }
    // GEMM3: out = feature @ out_w^T + out_b   -> d_out (16384 x 1024)
    {
        dim3 grid(D_DIM / 128, M_TOK / 128);
        gemm_tn_kernel<0><<<grid, 256>>>(p_h, out_w, out_b, out, M_TOK, D_DIM, TWO_D);
    }
}

// round 3
// speedup vs baseline: 1.6315x; 1.6315x over previous
#include <cuda_runtime.h>
#include <math.h>
#include <stdint.h>

// Problem constants (fixed: b=4, n=4096, d=1024)
#define B_BATCH 4
#define N_SEQ   4096
#define D_DIM   1024
#define M_TOK   (B_BATCH * N_SEQ)   // 16384
#define TWO_D   (2 * D_DIM)         // 2048

// Scratch (device globals; allocation-free per harness rules)
__device__ float g_is[(size_t)M_TOK * TWO_D];  // input_state
__device__ float g_nu[(size_t)M_TOK * D_DIM];  // sigmoid(nu)
__device__ float g_h [(size_t)M_TOK * TWO_D];  // [h_r | h_i]

// ---------------------------------------------------------------------------
// TF32 tensor-core GEMM:  C[M,N] = A[M,K] @ W[N,K]^T + bias[N]
// CTA tile 128x128x16, 256 threads = 8 warps (4 m-warps x 2 n-warps),
// warp tile 32x64, mma.sync m16n8k8 tf32, cp.async double buffer.
// Requires M%128==0, N%128==0, K%16==0 (true for all three GEMMs here).
// ---------------------------------------------------------------------------
#define BM 128
#define BN 128
#define BK 16
#define SPAD 4
#define SSTR (BK + SPAD)   // 20 floats per row -> conflict-free frag loads

__device__ __forceinline__ uint32_t f2tf32(float x) {
    uint32_t r;
    asm volatile("cvt.rna.tf32.f32 %0, %1;" : "=r"(r) : "f"(x));
    return r;
}

__device__ __forceinline__ void mma_tf32(float c[4], const uint32_t a[4], const uint32_t b[2]) {
    asm volatile(
        "mma.sync.aligned.m16n8k8.row.col.f32.tf32.tf32.f32 "
        "{%0,%1,%2,%3}, {%4,%5,%6,%7}, {%8,%9}, {%0,%1,%2,%3};"
        : "+f"(c[0]), "+f"(c[1]), "+f"(c[2]), "+f"(c[3])
        : "r"(a[0]), "r"(a[1]), "r"(a[2]), "r"(a[3]), "r"(b[0]), "r"(b[1]));
}

__device__ __forceinline__ void cp_async16(void* smem_ptr, const void* gmem_ptr) {
    uint32_t saddr = (uint32_t)__cvta_generic_to_shared(smem_ptr);
    asm volatile("cp.async.ca.shared.global [%0], [%1], 16;" :: "r"(saddr), "l"(gmem_ptr));
}
__device__ __forceinline__ void cp_commit()  { asm volatile("cp.async.commit_group;"); }
__device__ __forceinline__ void cp_wait0()   { asm volatile("cp.async.wait_group 0;"); }

template <int ACT>
__global__ __launch_bounds__(256)
void gemm_tf32_kernel(const float* __restrict__ A,
                      const float* __restrict__ W,
                      const float* __restrict__ bias,
                      float* __restrict__ C,
                      int M, int N, int K) {
    __shared__ float sA[2][BM * SSTR];
    __shared__ float sB[2][BN * SSTR];

    const int tid    = threadIdx.x;
    const int lane   = tid & 31;
    const int warp   = tid >> 5;
    const int grp    = lane >> 2;   // 0..7
    const int tig    = lane & 3;    // 0..3
    const int warp_m = warp & 3;    // 0..3  -> 32-row slice
    const int warp_n = warp >> 2;   // 0..1  -> 64-col slice

    const int bm = blockIdx.y * BM;
    const int bn = blockIdx.x * BN;

    // Loader mapping: 2 float4 per thread for each of A and B per k-tile
    const int lrow = tid >> 1;           // 0..127
    const int lk4  = (tid & 1) * 4;      // 0 or 4 (floats)

    const float* Ag = A + (size_t)(bm + lrow) * K + lk4;
    const float* Wg = W + (size_t)(bn + lrow) * K + lk4;
    float* sArow = &sA[0][lrow * SSTR + lk4];
    float* sBrow = &sB[0][lrow * SSTR + lk4];

    float acc[2][8][4];
#pragma unroll
    for (int i = 0; i < 2; i++)
#pragma unroll
        for (int j = 0; j < 8; j++)
#pragma unroll
            for (int v = 0; v < 4; v++) acc[i][j][v] = 0.0f;

    const int KT = K >> 4;  // k-tiles of 16

    // Prologue: load tile 0 into buffer 0
    cp_async16(sArow,              Ag);
    cp_async16(sArow + 8,          Ag + 8);
    cp_async16(sBrow,              Wg);
    cp_async16(sBrow + 8,          Wg + 8);
    cp_commit();

    const int bufstride_f = BM * SSTR;  // same for A and B (BM==BN)

    for (int kt = 0; kt < KT; kt++) {
        cp_wait0();
        __syncthreads();

        // Prefetch next k-tile into the other buffer
        if (kt + 1 < KT) {
            const float* Agn = Ag + (size_t)(kt + 1) * BK;
            const float* Wgn = Wg + (size_t)(kt + 1) * BK;
            float* dA = sArow + ((kt + 1) & 1) * bufstride_f;
            float* dB = sBrow + ((kt + 1) & 1) * bufstride_f;
            cp_async16(dA,     Agn);
            cp_async16(dA + 8, Agn + 8);
            cp_async16(dB,     Wgn);
            cp_async16(dB + 8, Wgn + 8);
            cp_commit();
        } else {
            cp_commit();  // keep wait_group accounting uniform
        }

        const float* As = &sA[kt & 1][0];
        const float* Bs = &sB[kt & 1][0];

#pragma unroll
        for (int kk = 0; kk < BK; kk += 8) {
            uint32_t afrag[2][4];
#pragma unroll
            for (int mf = 0; mf < 2; mf++) {
                const int r0 = warp_m * 32 + mf * 16 + grp;
                afrag[mf][0] = f2tf32(As[r0 * SSTR + kk + tig]);
                afrag[mf][1] = f2tf32(As[(r0 + 8) * SSTR + kk + tig]);
                afrag[mf][2] = f2tf32(As[r0 * SSTR + kk + tig + 4]);
                afrag[mf][3] = f2tf32(As[(r0 + 8) * SSTR + kk + tig + 4]);
            }
            uint32_t bfrag[8][2];
#pragma unroll
            for (int nf = 0; nf < 8; nf++) {
                const int c0 = warp_n * 64 + nf * 8 + grp;
                bfrag[nf][0] = f2tf32(Bs[c0 * SSTR + kk + tig]);
                bfrag[nf][1] = f2tf32(Bs[c0 * SSTR + kk + tig + 4]);
            }
#pragma unroll
            for (int mf = 0; mf < 2; mf++)
#pragma unroll
                for (int nf = 0; nf < 8; nf++)
                    mma_tf32(acc[mf][nf], afrag[mf], bfrag[nf]);
        }
        __syncthreads();
    }

    // Epilogue: bias (+sigmoid), vectorized float2 stores
#pragma unroll
    for (int mf = 0; mf < 2; mf++) {
#pragma unroll
        for (int half = 0; half < 2; half++) {   // c0/c1 vs c2/c3
            const int row = bm + warp_m * 32 + mf * 16 + grp + half * 8;
            float* Crow = C + (size_t)row * N;
#pragma unroll
            for (int nf = 0; nf < 8; nf++) {
                const int col = bn + warp_n * 64 + nf * 8 + tig * 2;
                float v0 = acc[mf][nf][half * 2 + 0] + bias[col];
                float v1 = acc[mf][nf][half * 2 + 1] + bias[col + 1];
                if (ACT == 1) {
                    v0 = 1.0f / (1.0f + expf(-v0));
                    v1 = 1.0f / (1.0f + expf(-v1));
                }
                *reinterpret_cast<float2*>(Crow + col) = make_float2(v0, v1);
            }
        }
    }
}

// ---------------------------------------------------------------------------
// Sequential diagonal complex scan: one thread per (batch, channel)
// ---------------------------------------------------------------------------
__global__ __launch_bounds__(128)
void scan_kernel(const float* __restrict__ theta_log,
                 const float* __restrict__ gamma_log) {
    const int gid = blockIdx.x * blockDim.x + threadIdx.x;  // 0..4095
    if (gid >= B_BATCH * D_DIM) return;
    const int b = gid >> 10;
    const int j = gid & (D_DIM - 1);

    const float theta = expf(theta_log[j]);
    const float ct = cosf(theta);
    const float st = sinf(theta);
    const float gm = expf(gamma_log[j]);

    float hr = 0.0f, hi = 0.0f;

    size_t nu_ofs = (size_t)b * N_SEQ * D_DIM + j;
    size_t is_ofs = (size_t)b * N_SEQ * TWO_D + 2 * j;
    size_t h_ofs  = (size_t)b * N_SEQ * TWO_D + j;

    for (int t = 0; t < N_SEQ; t++) {
        const float nu = g_nu[nu_ofs];
        const float2 uv = *reinterpret_cast<const float2*>(&g_is[is_ofs]);
        const float lr = nu * ct;
        const float li = nu * st;
        const float nhr = lr * hr - li * hi + gm * uv.x;
        const float nhi = lr * hi + li * hr + gm * uv.y;
        hr = nhr; hi = nhi;
        g_h[h_ofs]         = hr;
        g_h[h_ofs + D_DIM] = hi;
        nu_ofs += D_DIM;
        is_ofs += TWO_D;
        h_ofs  += TWO_D;
    }
}

// ---------------------------------------------------------------------------
// Launch
// ---------------------------------------------------------------------------
extern "C" void kernel_launch(void* const* d_in, const int* in_sizes, int n_in,
                              void* d_out, int out_size) {
    const float* x         = (const float*)d_in[0];
    const float* theta_log = (const float*)d_in[1];
    const float* gamma_log = (const float*)d_in[2];
    const float* nu_w      = (const float*)d_in[3];
    const float* nu_b      = (const float*)d_in[4];
    const float* in_w      = (const float*)d_in[5];
    const float* in_b      = (const float*)d_in[6];
    const float* out_w     = (const float*)d_in[7];
    const float* out_b     = (const float*)d_in[8];
    float* out = (float*)d_out;

    float *p_is = nullptr, *p_nu = nullptr, *p_h = nullptr;
    cudaGetSymbolAddress((void**)&p_is, g_is);
    cudaGetSymbolAddress((void**)&p_nu, g_nu);
    cudaGetSymbolAddress((void**)&p_h,  g_h);

    // GEMM1: input_state = x @ in_w^T + in_b   (16384 x 2048, K=1024)
    {
        dim3 grid(TWO_D / BN, M_TOK / BM);
        gemm_tf32_kernel<0><<<grid, 256>>>(x, in_w, in_b, p_is, M_TOK, TWO_D, D_DIM);
    }
    // GEMM2: nu = sigmoid(x @ nu_w^T + nu_b)   (16384 x 1024, K=1024)
    {
        dim3 grid(D_DIM / BN, M_TOK / BM);
        gemm_tf32_kernel<1><<<grid, 256>>>(x, nu_w, nu_b, p_nu, M_TOK, D_DIM, D_DIM);
    }
    // Scan -> g_h
    scan_kernel<<<(B_BATCH * D_DIM) / 128, 128>>>(theta_log, gamma_log);
    // GEMM3: out = [h_r|h_i] @ out_w^T + out_b (16384 x 1024, K=2048)
    {
        dim3 grid(D_DIM / BN, M_TOK / BM);
        gemm_tf32_kernel<0><<<grid, 256>>>(p_h, out_w, out_b, out, M_TOK, D_DIM, TWO_D);
    }
}

// round 9
// speedup vs baseline: 3.3728x; 2.0674x over previous
#include <cuda_runtime.h>
#include <math.h>
#include <stdint.h>

// Problem constants (fixed: b=4, n=4096, d=1024)
#define B_BATCH 4
#define N_SEQ   4096
#define D_DIM   1024
#define M_TOK   (B_BATCH * N_SEQ)   // 16384
#define TWO_D   (2 * D_DIM)         // 2048

// Chunked scan: 64 chunks of 64 timesteps
#define NCHUNK 64
#define CLEN   64

// ---------------------------------------------------------------------------
// Scratch (device globals; allocation-free per harness rules)
// ---------------------------------------------------------------------------
__device__ float g_is[(size_t)M_TOK * TWO_D];    // input_state fp32 (128MB)
__device__ float g_nu[(size_t)M_TOK * D_DIM];    // sigmoid(nu) fp32 (64MB)
__device__ float g_h [(size_t)M_TOK * TWO_D];    // [h_r|h_i], tf32-rounded (128MB)
__device__ float g_xr [(size_t)M_TOK * D_DIM];   // x  tf32-rounded (64MB)
__device__ float g_iwr[(size_t)TWO_D * D_DIM];   // in_w  rounded (8MB)
__device__ float g_nwr[(size_t)D_DIM * D_DIM];   // nu_w  rounded (4MB)
__device__ float g_owr[(size_t)D_DIM * TWO_D];   // out_w rounded (8MB)
__device__ float2 g_A[(size_t)B_BATCH * NCHUNK * D_DIM];  // chunk lambda products
__device__ float2 g_E[(size_t)B_BATCH * NCHUNK * D_DIM];  // chunk local end states
__device__ float2 g_S[(size_t)B_BATCH * NCHUNK * D_DIM];  // chunk start states

// ---------------------------------------------------------------------------
// Helpers
// ---------------------------------------------------------------------------
__device__ __forceinline__ float f2tf32f(float x) {
    uint32_t r;
    asm volatile("cvt.rna.tf32.f32 %0, %1;" : "=r"(r) : "f"(x));
    return __uint_as_float(r);
}
__device__ __forceinline__ void mma_tf32(float c[4], const uint32_t a[4], const uint32_t b[2]) {
    asm volatile(
        "mma.sync.aligned.m16n8k8.row.col.f32.tf32.tf32.f32 "
        "{%0,%1,%2,%3}, {%4,%5,%6,%7}, {%8,%9}, {%0,%1,%2,%3};"
        : "+f"(c[0]), "+f"(c[1]), "+f"(c[2]), "+f"(c[3])
        : "r"(a[0]), "r"(a[1]), "r"(a[2]), "r"(a[3]), "r"(b[0]), "r"(b[1]));
}
__device__ __forceinline__ void cp_async16(void* smem_ptr, const void* gmem_ptr) {
    uint32_t saddr = (uint32_t)__cvta_generic_to_shared(smem_ptr);
    asm volatile("cp.async.ca.shared.global [%0], [%1], 16;" :: "r"(saddr), "l"(gmem_ptr));
}
__device__ __forceinline__ void cp_commit() { asm volatile("cp.async.commit_group;"); }
__device__ __forceinline__ void cp_wait0()  { asm volatile("cp.async.wait_group 0;"); }

// ---------------------------------------------------------------------------
// TF32 rounding pass: dst[i] = round_rna_tf32(src[i])  (vectorized)
// ---------------------------------------------------------------------------
__global__ __launch_bounds__(256)
void round_tf32_kernel(const float* __restrict__ src, float* __restrict__ dst, int n4) {
    int i = blockIdx.x * blockDim.x + threadIdx.x;
    const int stride = gridDim.x * blockDim.x;
    for (; i < n4; i += stride) {
        float4 v = reinterpret_cast<const float4*>(src)[i];
        v.x = f2tf32f(v.x); v.y = f2tf32f(v.y);
        v.z = f2tf32f(v.z); v.w = f2tf32f(v.w);
        reinterpret_cast<float4*>(dst)[i] = v;
    }
}

// ---------------------------------------------------------------------------
// TF32 tensor GEMM:  C[M,N] = A[M,K] @ W[N,K]^T + bias[N]  (ACT=1: sigmoid)
// Inputs pre-rounded to tf32 (loaded as raw bit patterns; no cvt inner loop).
// CTA 128x128x16, 256 threads, warp tile 32x64, cp.async double buffer.
// ---------------------------------------------------------------------------
#define BM 128
#define BN 128
#define BK 16
#define SSTR 20

template <int ACT>
__global__ __launch_bounds__(256)
void gemm_tf32_kernel(const float* __restrict__ A,
                      const float* __restrict__ W,
                      const float* __restrict__ bias,
                      float* __restrict__ C,
                      int M, int N, int K) {
    __shared__ float sA[2][BM * SSTR];
    __shared__ float sB[2][BN * SSTR];

    const int tid    = threadIdx.x;
    const int lane   = tid & 31;
    const int warp   = tid >> 5;
    const int grp    = lane >> 2;   // 0..7
    const int tig    = lane & 3;    // 0..3
    const int warp_m = warp & 3;    // 0..3
    const int warp_n = warp >> 2;   // 0..1

    const int bm = blockIdx.y * BM;
    const int bn = blockIdx.x * BN;

    const int lrow = tid >> 1;           // 0..127
    const int lk4  = (tid & 1) * 4;      // 0 or 4

    const float* Ag = A + (size_t)(bm + lrow) * K + lk4;
    const float* Wg = W + (size_t)(bn + lrow) * K + lk4;
    float* sArow = &sA[0][lrow * SSTR + lk4];
    float* sBrow = &sB[0][lrow * SSTR + lk4];

    float acc[2][8][4];
#pragma unroll
    for (int i = 0; i < 2; i++)
#pragma unroll
        for (int j = 0; j < 8; j++)
#pragma unroll
            for (int v = 0; v < 4; v++) acc[i][j][v] = 0.0f;

    const int KT = K >> 4;

    cp_async16(sArow,     Ag);
    cp_async16(sArow + 8, Ag + 8);
    cp_async16(sBrow,     Wg);
    cp_async16(sBrow + 8, Wg + 8);
    cp_commit();

    const int bufstride_f = BM * SSTR;

    for (int kt = 0; kt < KT; kt++) {
        cp_wait0();
        __syncthreads();

        if (kt + 1 < KT) {
            const float* Agn = Ag + (size_t)(kt + 1) * BK;
            const float* Wgn = Wg + (size_t)(kt + 1) * BK;
            float* dA = sArow + ((kt + 1) & 1) * bufstride_f;
            float* dB = sBrow + ((kt + 1) & 1) * bufstride_f;
            cp_async16(dA,     Agn);
            cp_async16(dA + 8, Agn + 8);
            cp_async16(dB,     Wgn);
            cp_async16(dB + 8, Wgn + 8);
            cp_commit();
        } else {
            cp_commit();
        }

        const float* As = &sA[kt & 1][0];
        const float* Bs = &sB[kt & 1][0];

#pragma unroll
        for (int kk = 0; kk < BK; kk += 8) {
            uint32_t afrag[2][4];
#pragma unroll
            for (int mf = 0; mf < 2; mf++) {
                const int r0 = warp_m * 32 + mf * 16 + grp;
                afrag[mf][0] = __float_as_uint(As[r0 * SSTR + kk + tig]);
                afrag[mf][1] = __float_as_uint(As[(r0 + 8) * SSTR + kk + tig]);
                afrag[mf][2] = __float_as_uint(As[r0 * SSTR + kk + tig + 4]);
                afrag[mf][3] = __float_as_uint(As[(r0 + 8) * SSTR + kk + tig + 4]);
            }
            uint32_t bfrag[8][2];
#pragma unroll
            for (int nf = 0; nf < 8; nf++) {
                const int c0 = warp_n * 64 + nf * 8 + grp;
                bfrag[nf][0] = __float_as_uint(Bs[c0 * SSTR + kk + tig]);
                bfrag[nf][1] = __float_as_uint(Bs[c0 * SSTR + kk + tig + 4]);
            }
#pragma unroll
            for (int mf = 0; mf < 2; mf++)
#pragma unroll
                for (int nf = 0; nf < 8; nf++)
                    mma_tf32(acc[mf][nf], afrag[mf], bfrag[nf]);
        }
        __syncthreads();
    }

#pragma unroll
    for (int mf = 0; mf < 2; mf++) {
#pragma unroll
        for (int half = 0; half < 2; half++) {
            const int row = bm + warp_m * 32 + mf * 16 + grp + half * 8;
            float* Crow = C + (size_t)row * N;
#pragma unroll
            for (int nf = 0; nf < 8; nf++) {
                const int col = bn + warp_n * 64 + nf * 8 + tig * 2;
                float v0 = acc[mf][nf][half * 2 + 0] + bias[col];
                float v1 = acc[mf][nf][half * 2 + 1] + bias[col + 1];
                if (ACT == 1) {
                    v0 = 1.0f / (1.0f + expf(-v0));
                    v1 = 1.0f / (1.0f + expf(-v1));
                }
                *reinterpret_cast<float2*>(Crow + col) = make_float2(v0, v1);
            }
        }
    }
}

// ---------------------------------------------------------------------------
// Chunked scan pass 1: per (b, chunk, j) compute lambda product A and
// zero-init local end state E over CLEN steps.  262144 threads.
// ---------------------------------------------------------------------------
__global__ __launch_bounds__(256)
void scan_pass1_kernel(const float* __restrict__ theta_log,
                       const float* __restrict__ gamma_log) {
    const int gid = blockIdx.x * blockDim.x + threadIdx.x;
    if (gid >= B_BATCH * NCHUNK * D_DIM) return;
    const int j = gid & (D_DIM - 1);
    const int c = (gid >> 10) & (NCHUNK - 1);
    const int b = gid >> 16;

    const float theta = expf(theta_log[j]);
    const float ct = cosf(theta);
    const float st = sinf(theta);
    const float gm = expf(gamma_log[j]);

    size_t nu_ofs = ((size_t)b * N_SEQ + (size_t)c * CLEN) * D_DIM + j;
    size_t is_ofs = ((size_t)b * N_SEQ + (size_t)c * CLEN) * TWO_D + 2 * j;

    float Ar = 1.0f, Ai = 0.0f, Er = 0.0f, Ei = 0.0f;
#pragma unroll 4
    for (int t = 0; t < CLEN; t++) {
        const float nu = g_nu[nu_ofs];
        const float2 uv = *reinterpret_cast<const float2*>(&g_is[is_ofs]);
        const float lr = nu * ct;
        const float li = nu * st;
        const float nEr = lr * Er - li * Ei + gm * uv.x;
        const float nEi = lr * Ei + li * Er + gm * uv.y;
        const float nAr = lr * Ar - li * Ai;
        const float nAi = lr * Ai + li * Ar;
        Er = nEr; Ei = nEi; Ar = nAr; Ai = nAi;
        nu_ofs += D_DIM;
        is_ofs += TWO_D;
    }
    g_A[gid] = make_float2(Ar, Ai);
    g_E[gid] = make_float2(Er, Ei);
}

// ---------------------------------------------------------------------------
// Chunk fix-up: per (b, j), sequentially combine the NCHUNK chunk summaries
// to produce each chunk's true start state.  4096 threads; data fits in L2.
// ---------------------------------------------------------------------------
__global__ __launch_bounds__(256)
void scan_fix_kernel() {
    const int gid = blockIdx.x * blockDim.x + threadIdx.x;
    if (gid >= B_BATCH * D_DIM) return;
    const int j = gid & (D_DIM - 1);
    const int b = gid >> 10;

    float sr = 0.0f, si = 0.0f;
#pragma unroll 4
    for (int c = 0; c < NCHUNK; c++) {
        const size_t idx = ((size_t)b * NCHUNK + c) * D_DIM + j;
        g_S[idx] = make_float2(sr, si);
        const float2 A = g_A[idx];
        const float2 E = g_E[idx];
        const float nr = A.x * sr - A.y * si + E.x;
        const float ni = A.x * si + A.y * sr + E.y;
        sr = nr; si = ni;
    }
}

// ---------------------------------------------------------------------------
// Chunked scan pass 2: re-run each chunk from its true start state; write
// h (tf32-rounded, GEMM3-ready) as [h_r | h_i] rows.
// ---------------------------------------------------------------------------
__global__ __launch_bounds__(256)
void scan_pass2_kernel(const float* __restrict__ theta_log,
                       const float* __restrict__ gamma_log) {
    const int gid = blockIdx.x * blockDim.x + threadIdx.x;
    if (gid >= B_BATCH * NCHUNK * D_DIM) return;
    const int j = gid & (D_DIM - 1);
    const int c = (gid >> 10) & (NCHUNK - 1);
    const int b = gid >> 16;

    const float theta = expf(theta_log[j]);
    const float ct = cosf(theta);
    const float st = sinf(theta);
    const float gm = expf(gamma_log[j]);

    const float2 s0 = g_S[gid];
    float hr = s0.x, hi = s0.y;

    size_t nu_ofs = ((size_t)b * N_SEQ + (size_t)c * CLEN) * D_DIM + j;
    size_t is_ofs = ((size_t)b * N_SEQ + (size_t)c * CLEN) * TWO_D + 2 * j;
    size_t h_ofs  = ((size_t)b * N_SEQ + (size_t)c * CLEN) * TWO_D + j;

#pragma unroll 4
    for (int t = 0; t < CLEN; t++) {
        const float nu = g_nu[nu_ofs];
        const float2 uv = *reinterpret_cast<const float2*>(&g_is[is_ofs]);
        const float lr = nu * ct;
        const float li = nu * st;
        const float nhr = lr * hr - li * hi + gm * uv.x;
        const float nhi = lr * hi + li * hr + gm * uv.y;
        hr = nhr; hi = nhi;
        g_h[h_ofs]         = f2tf32f(hr);
        g_h[h_ofs + D_DIM] = f2tf32f(hi);
        nu_ofs += D_DIM;
        is_ofs += TWO_D;
        h_ofs  += TWO_D;
    }
}

// ---------------------------------------------------------------------------
// Launch
// ---------------------------------------------------------------------------
extern "C" void kernel_launch(void* const* d_in, const int* in_sizes, int n_in,
                              void* d_out, int out_size) {
    const float* x         = (const float*)d_in[0];
    const float* theta_log = (const float*)d_in[1];
    const float* gamma_log = (const float*)d_in[2];
    const float* nu_w      = (const float*)d_in[3];
    const float* nu_b      = (const float*)d_in[4];
    const float* in_w      = (const float*)d_in[5];
    const float* in_b      = (const float*)d_in[6];
    const float* out_w     = (const float*)d_in[7];
    const float* out_b     = (const float*)d_in[8];
    float* out = (float*)d_out;

    float *p_is, *p_nu, *p_h, *p_xr, *p_iwr, *p_nwr, *p_owr;
    cudaGetSymbolAddress((void**)&p_is,  g_is);
    cudaGetSymbolAddress((void**)&p_nu,  g_nu);
    cudaGetSymbolAddress((void**)&p_h,   g_h);
    cudaGetSymbolAddress((void**)&p_xr,  g_xr);
    cudaGetSymbolAddress((void**)&p_iwr, g_iwr);
    cudaGetSymbolAddress((void**)&p_nwr, g_nwr);
    cudaGetSymbolAddress((void**)&p_owr, g_owr);

    // TF32 pre-rounding (x + weights)
    round_tf32_kernel<<<2048, 256>>>(x,     p_xr,  (M_TOK * D_DIM) / 4);
    round_tf32_kernel<<<512,  256>>>(in_w,  p_iwr, (TWO_D * D_DIM) / 4);
    round_tf32_kernel<<<256,  256>>>(nu_w,  p_nwr, (D_DIM * D_DIM) / 4);
    round_tf32_kernel<<<512,  256>>>(out_w, p_owr, (D_DIM * TWO_D) / 4);

    // GEMM1: input_state = x @ in_w^T + in_b   (16384 x 2048, K=1024)
    {
        dim3 grid(TWO_D / BN, M_TOK / BM);
        gemm_tf32_kernel<0><<<grid, 256>>>(p_xr, p_iwr, in_b, p_is, M_TOK, TWO_D, D_DIM);
    }
    // GEMM2: nu = sigmoid(x @ nu_w^T + nu_b)   (16384 x 1024, K=1024)
    {
        dim3 grid(D_DIM / BN, M_TOK / BM);
        gemm_tf32_kernel<1><<<grid, 256>>>(p_xr, p_nwr, nu_b, p_nu, M_TOK, D_DIM, D_DIM);
    }
    // Chunked parallel scan
    scan_pass1_kernel<<<(B_BATCH * NCHUNK * D_DIM) / 256, 256>>>(theta_log, gamma_log);
    scan_fix_kernel<<<(B_BATCH * D_DIM + 255) / 256, 256>>>();
    scan_pass2_kernel<<<(B_BATCH * NCHUNK * D_DIM) / 256, 256>>>(theta_log, gamma_log);
    // GEMM3: out = [h_r|h_i] @ out_w^T + out_b (16384 x 1024, K=2048)
    {
        dim3 grid(D_DIM / BN, M_TOK / BM);
        gemm_tf32_kernel<0><<<grid, 256>>>(p_h, p_owr, out_b, out, M_TOK, D_DIM, TWO_D);
    }
}